// round 14
// baseline (speedup 1.0000x reference)
#include <cuda_runtime.h>
#include <cuda_fp16.h>
#include <math_constants.h>
#include <cstdint>
#include <cstddef>

#define BB 2
#define NQ 4096
#define NKV 1024
#define DD 512
#define HH 8
#define DH 64
#define LN_EPS 1e-5f

// ---------------------------------------------------------------------------
// Scratch
// ---------------------------------------------------------------------------
__device__ __half g_kh[BB * NKV * DD];
__device__ __half g_vh[BB * NKV * DD];
__device__ __half g_attn[BB * NQ * DD];
__device__ float2 g_psum[BB * NQ * HH];
__device__ __half g_wt[4 * DD * DD];     // W^T fp16 (Wq/8, Wo*gamma folded)
__device__ float2 g_uvpart[8 * DD];
__device__ float  g_u[DD];
__device__ float  g_vb[DD];

// ---------------------------------------------------------------------------
// helpers
// ---------------------------------------------------------------------------
__device__ __forceinline__ uint32_t packh2(float lo, float hi) {
    uint32_t r;
    asm("cvt.rn.f16x2.f32 %0, %1, %2;" : "=r"(r) : "f"(hi), "f"(lo));
    return r;
}

__device__ __forceinline__ void mma_f16(float d[4], const uint32_t a[4],
                                        const uint32_t b[2]) {
    asm("mma.sync.aligned.m16n8k16.row.col.f32.f16.f16.f32 "
        "{%0,%1,%2,%3},{%4,%5,%6,%7},{%8,%9},{%0,%1,%2,%3};"
        : "+f"(d[0]), "+f"(d[1]), "+f"(d[2]), "+f"(d[3])
        : "r"(a[0]), "r"(a[1]), "r"(a[2]), "r"(a[3]), "r"(b[0]), "r"(b[1]));
}

// ---------------------------------------------------------------------------
// Weight transpose + fp16 convert: Wt[z][n][k] = fp16(W_z[k][n] * scale_z(k))
// ---------------------------------------------------------------------------
__global__ void __launch_bounds__(256) transpose_w(
    const float* __restrict__ Wq, const float* __restrict__ Wk,
    const float* __restrict__ Wv, const float* __restrict__ Wo,
    const float* __restrict__ gamma, __half* __restrict__ Wt)
{
    __shared__ float t[32][33];
    const int z = blockIdx.z;
    const float* W = (z == 0) ? Wq : (z == 1) ? Wk : (z == 2) ? Wv : Wo;
    __half* T = Wt + (size_t)z * DD * DD;
    const int tx = threadIdx.x, ty = threadIdx.y;
    const int kb = blockIdx.x * 32, nb = blockIdx.y * 32;
    #pragma unroll
    for (int j = 0; j < 4; j++) {
        const int k = kb + ty + j * 8;
        float sc = 1.0f;
        if (z == 0) sc = 0.125f;
        else if (z == 3) sc = gamma[k];
        t[ty + j * 8][tx] = W[(size_t)k * DD + nb + tx] * sc;
    }
    __syncthreads();
    #pragma unroll
    for (int j = 0; j < 4; j++)
        T[(size_t)(nb + ty + j * 8) * DD + kb + tx] =
            __float2half_rn(t[tx][ty + j * 8]);
}

// ---------------------------------------------------------------------------
// Split-K u/v partials + reduce
// ---------------------------------------------------------------------------
__global__ void __launch_bounds__(256) uv_part(
    const float* __restrict__ Wo, const float* __restrict__ gamma,
    const float* __restrict__ beta, float2* __restrict__ part)
{
    const int n = blockIdx.x * 256 + threadIdx.x;
    const int ks = blockIdx.y * 64;
    float su = 0.f, sv = 0.f;
    #pragma unroll 4
    for (int k = ks; k < ks + 64; k++) {
        const float w = Wo[(size_t)k * DD + n];
        su = fmaf(gamma[k], w, su);
        sv = fmaf(beta[k], w, sv);
    }
    part[blockIdx.y * DD + n] = make_float2(su, sv);
}

__global__ void __launch_bounds__(256) uv_reduce(
    const float2* __restrict__ part, const float* __restrict__ bo,
    float* __restrict__ u, float* __restrict__ vb)
{
    const int n = blockIdx.x * 256 + threadIdx.x;
    float su = 0.f, sv = 0.f;
    #pragma unroll
    for (int s = 0; s < 8; s++) {
        const float2 p = part[s * DD + n];
        su += p.x; sv += p.y;
    }
    u[n] = su;
    vb[n] = sv + bo[n];
}

// ---------------------------------------------------------------------------
// K/V projection GEMM (fp16 out), double-buffered. grid (4, 32):
// y<16 -> K rows y*128; else V rows (y-16)*128. Single wave (128 CTAs).
// ---------------------------------------------------------------------------
__global__ void __launch_bounds__(256) proj_gemm(
    const float* __restrict__ Akv,
    const __half* __restrict__ WtK, const __half* __restrict__ WtV,
    __half* __restrict__ Ck, __half* __restrict__ Cv)
{
    __shared__ uint32_t As[2][128 * 20];
    __shared__ uint32_t Bs[2][128 * 20];

    const int ty = blockIdx.y;
    const __half* __restrict__ Wt = (ty < 16) ? WtK : WtV;
    __half* __restrict__ C = (ty < 16) ? Ck : Cv;
    const int row0 = ((ty < 16) ? ty : (ty - 16)) * 128;

    const int tid = threadIdx.x;
    const int lane = tid & 31;
    const int g = lane >> 2, t = lane & 3;
    const int w = tid >> 5;
    const int wm = w >> 1, wn = w & 1;
    const int col0 = blockIdx.x * 128;

    const int ar = tid >> 3;
    const int af4 = tid & 7;
    const int br = tid >> 2;
    const int bf = tid & 3;

    float4 aR[4];
    uint4 bR[2];

    auto loadA = [&](int k0) {
        #pragma unroll
        for (int i = 0; i < 4; i++)
            aR[i] = *(const float4*)(Akv + (size_t)(row0 + ar + i * 32) * DD + k0 + af4 * 4);
    };
    auto loadB = [&](int k0) {
        #pragma unroll
        for (int i = 0; i < 2; i++)
            bR[i] = *(const uint4*)(Wt + (size_t)(col0 + br + i * 64) * DD + k0 + bf * 8);
    };

    float acc[2][8][4];
    #pragma unroll
    for (int mi = 0; mi < 2; mi++)
        #pragma unroll
        for (int ni = 0; ni < 8; ni++)
            #pragma unroll
            for (int r = 0; r < 4; r++) acc[mi][ni][r] = 0.f;

    loadA(0);
    loadB(0);

    #pragma unroll 1
    for (int s = 0; s < 16; s++) {
        const int buf = s & 1;
        #pragma unroll
        for (int i = 0; i < 4; i++)
            *(uint2*)&As[buf][(ar + i * 32) * 20 + af4 * 2] =
                make_uint2(packh2(aR[i].x, aR[i].y), packh2(aR[i].z, aR[i].w));
        #pragma unroll
        for (int i = 0; i < 2; i++)
            *(uint4*)&Bs[buf][(br + i * 64) * 20 + bf * 4] = bR[i];
        __syncthreads();

        if (s < 15) { loadA((s + 1) * 32); loadB((s + 1) * 32); }

        #pragma unroll
        for (int ks = 0; ks < 2; ks++) {
            const int ko = ks * 8;
            uint32_t af[2][4];
            #pragma unroll
            for (int mi = 0; mi < 2; mi++) {
                const int mb = wm * 32 + mi * 16;
                af[mi][0] = As[buf][(mb + g) * 20 + ko + t];
                af[mi][1] = As[buf][(mb + g + 8) * 20 + ko + t];
                af[mi][2] = As[buf][(mb + g) * 20 + ko + t + 4];
                af[mi][3] = As[buf][(mb + g + 8) * 20 + ko + t + 4];
            }
            #pragma unroll
            for (int ni = 0; ni < 8; ni++) {
                const int nb = wn * 64 + ni * 8;
                uint32_t bf2[2];
                bf2[0] = Bs[buf][(nb + g) * 20 + ko + t];
                bf2[1] = Bs[buf][(nb + g) * 20 + ko + t + 4];
                mma_f16(acc[0][ni], af[0], bf2);
                mma_f16(acc[1][ni], af[1], bf2);
            }
        }
    }

    #pragma unroll
    for (int mi = 0; mi < 2; mi++) {
        const int rr0 = row0 + wm * 32 + mi * 16 + g;
        #pragma unroll
        for (int ni = 0; ni < 8; ni++) {
            const int cc = col0 + wn * 64 + ni * 8 + 2 * t;
            *(uint32_t*)(C + (size_t)rr0 * DD + cc) =
                packh2(acc[mi][ni][0], acc[mi][ni][1]);
            *(uint32_t*)(C + (size_t)(rr0 + 8) * DD + cc) =
                packh2(acc[mi][ni][2], acc[mi][ni][3]);
        }
    }
}

// ---------------------------------------------------------------------------
// Output GEMM, LN factored: C = rs*(A@W') + sh*u + vb (round-13 proven).
// ---------------------------------------------------------------------------
__global__ void __launch_bounds__(256) out_gemm(
    const __half* __restrict__ A, const __half* __restrict__ Wt,
    const float* __restrict__ u, const float* __restrict__ vb,
    const float2* __restrict__ psum, float* __restrict__ C)
{
    __shared__ uint32_t As[2][128 * 20];
    __shared__ uint32_t Bs[2][128 * 20];

    const int tid = threadIdx.x;
    const int lane = tid & 31;
    const int g = lane >> 2, t = lane & 3;
    const int w = tid >> 5;
    const int wm = w >> 1, wn = w & 1;
    const int row0 = blockIdx.y * 128, col0 = blockIdx.x * 128;

    const int cr = tid >> 2;
    const int co = tid & 3;

    float rs_[2][2], sh_[2][2];
    #pragma unroll
    for (int mi = 0; mi < 2; mi++)
        #pragma unroll
        for (int hh = 0; hh < 2; hh++) {
            const int gr = row0 + wm * 32 + mi * 16 + hh * 8 + g;
            float S = 0.f, Q = 0.f;
            #pragma unroll
            for (int hd = 0; hd < HH; hd++) {
                const float2 ps = psum[gr * HH + hd];
                S += ps.x; Q += ps.y;
            }
            const float mean = S * (1.f / DD);
            const float var = Q * (1.f / DD) - mean * mean;
            const float rs = rsqrtf(var + LN_EPS);
            rs_[mi][hh] = rs;
            sh_[mi][hh] = -mean * rs;
        }

    uint4 aR[2], bR[2];

    auto loadAB = [&](int k0) {
        #pragma unroll
        for (int i = 0; i < 2; i++) {
            aR[i] = *(const uint4*)(A + (size_t)(row0 + cr + i * 64) * DD + k0 + co * 8);
            bR[i] = *(const uint4*)(Wt + (size_t)(col0 + cr + i * 64) * DD + k0 + co * 8);
        }
    };

    float acc[2][8][4];
    #pragma unroll
    for (int mi = 0; mi < 2; mi++)
        #pragma unroll
        for (int ni = 0; ni < 8; ni++)
            #pragma unroll
            for (int r = 0; r < 4; r++) acc[mi][ni][r] = 0.f;

    loadAB(0);

    #pragma unroll 1
    for (int s = 0; s < 16; s++) {
        const int buf = s & 1;
        #pragma unroll
        for (int i = 0; i < 2; i++) {
            *(uint4*)&As[buf][(cr + i * 64) * 20 + co * 4] = aR[i];
            *(uint4*)&Bs[buf][(cr + i * 64) * 20 + co * 4] = bR[i];
        }
        __syncthreads();

        if (s < 15) loadAB((s + 1) * 32);

        #pragma unroll
        for (int ks = 0; ks < 2; ks++) {
            const int ko = ks * 8;
            uint32_t af[2][4];
            #pragma unroll
            for (int mi = 0; mi < 2; mi++) {
                const int mb = wm * 32 + mi * 16;
                af[mi][0] = As[buf][(mb + g) * 20 + ko + t];
                af[mi][1] = As[buf][(mb + g + 8) * 20 + ko + t];
                af[mi][2] = As[buf][(mb + g) * 20 + ko + t + 4];
                af[mi][3] = As[buf][(mb + g + 8) * 20 + ko + t + 4];
            }
            #pragma unroll
            for (int ni = 0; ni < 8; ni++) {
                const int nb = wn * 64 + ni * 8;
                uint32_t bf2[2];
                bf2[0] = Bs[buf][(nb + g) * 20 + ko + t];
                bf2[1] = Bs[buf][(nb + g) * 20 + ko + t + 4];
                mma_f16(acc[0][ni], af[0], bf2);
                mma_f16(acc[1][ni], af[1], bf2);
            }
        }
    }

    #pragma unroll
    for (int mi = 0; mi < 2; mi++) {
        const int rr0 = row0 + wm * 32 + mi * 16 + g;
        #pragma unroll
        for (int ni = 0; ni < 8; ni++) {
            const int cc = col0 + wn * 64 + ni * 8 + 2 * t;
            const float2 u2 = *(const float2*)(u + cc);
            const float2 vb2 = *(const float2*)(vb + cc);
            float2 v0, v1;
            v0.x = fmaf(acc[mi][ni][0], rs_[mi][0], fmaf(sh_[mi][0], u2.x, vb2.x));
            v0.y = fmaf(acc[mi][ni][1], rs_[mi][0], fmaf(sh_[mi][0], u2.y, vb2.y));
            v1.x = fmaf(acc[mi][ni][2], rs_[mi][1], fmaf(sh_[mi][1], u2.x, vb2.x));
            v1.y = fmaf(acc[mi][ni][3], rs_[mi][1], fmaf(sh_[mi][1], u2.y, vb2.y));
            *(float2*)(C + (size_t)rr0 * DD + cc) = v0;
            *(float2*)(C + (size_t)(rr0 + 8) * DD + cc) = v1;
        }
    }
}

// ---------------------------------------------------------------------------
// Flash attention with FUSED Q-PROJECTION prologue.
// Prologue: Qs[128][64] = q_tile[128x512](fp32) @ WtQ[h*64..][512] via
// 16-stage double-buffered mini-GEMM staged in the (not-yet-used) KsB/VsB
// smem. Then the round-11 main loop (reg prefetch + double-buffered K/V,
// online softmax, fp16 O + LN partial sums). K/V chunk-0 loads are issued
// before the prologue so their latency hides under the mini-GEMM.
// ---------------------------------------------------------------------------
#define ATTN_SMEM_BYTES ((128 * 36 + 2 * 64 * 36 + 2 * 32 * 68) * 4)

__global__ void __launch_bounds__(256, 2) attn_f16(
    const float* __restrict__ Qf, const __half* __restrict__ WtQ,
    const __half* __restrict__ Kh, const __half* __restrict__ Vh,
    __half* __restrict__ O, float2* __restrict__ psum)
{
    extern __shared__ uint32_t smd[];
    uint32_t* Qs  = smd;                 // 128*36
    uint32_t* KsB = Qs + 128 * 36;       // 2 x 64*36
    uint32_t* VsB = KsB + 2 * 64 * 36;   // 2 x 32*68

    const int tile = (NQ / 128 - 1) - blockIdx.x;
    const int h = blockIdx.y, b = blockIdx.z;
    const int tid = threadIdx.x;
    const int lane = tid & 31;
    const int g = lane >> 2, t = lane & 3;
    const int w = tid >> 5;
    const int wm = w >> 1, wn = w & 1;

    const size_t qbase = ((size_t)b * NQ + (size_t)tile * 128) * DD + (size_t)h * DH;
    const size_t kvbase = (size_t)b * NKV * DD + (size_t)h * DH;

    const int nch = (32 * tile + 95) >> 6;

    // K/V prefetch geometry + registers (chunk 0 issued before prologue)
    const int kr8 = tid >> 3, kc8 = tid & 7;
    const int vjp = tid >> 4, vd4 = tid & 15;
    uint4 kR[2];
    uint2 vaR[2], vbR[2];

    auto loadKV = [&](int k0) {
        #pragma unroll
        for (int i = 0; i < 2; i++)
            kR[i] = *(const uint4*)(Kh + kvbase + (size_t)(k0 + kr8 + i * 32) * DD + kc8 * 8);
        #pragma unroll
        for (int i = 0; i < 2; i++) {
            const int jp = vjp + i * 16;
            vaR[i] = *(const uint2*)(Vh + kvbase + (size_t)(k0 + 2 * jp) * DD + vd4 * 4);
            vbR[i] = *(const uint2*)(Vh + kvbase + (size_t)(k0 + 2 * jp + 1) * DD + vd4 * 4);
        }
    };

    loadKV(0);

    // ---- Q-projection prologue ----
    {
        uint32_t* As0 = KsB;             // 2560 words each
        uint32_t* As1 = KsB + 2560;
        uint32_t* Bs0 = KsB + 5120;      // 1280 words each
        uint32_t* Bs1 = KsB + 6400;      // ends 7680 <= 8960 (KsB+VsB)

        const int ar = tid >> 3;         // rows + i*32
        const int af4 = tid & 7;
        const int br = tid >> 2;         // 0..63
        const int bf = tid & 3;

        const float* Aq = Qf + ((size_t)b * NQ + (size_t)tile * 128) * DD;
        const __half* Bw = WtQ + (size_t)(h * DH) * DD;

        float4 aR[4];
        uint4 bR;
        auto loadQA = [&](int k0) {
            #pragma unroll
            for (int i = 0; i < 4; i++)
                aR[i] = *(const float4*)(Aq + (size_t)(ar + i * 32) * DD + k0 + af4 * 4);
        };
        auto loadQB = [&](int k0) {
            bR = *(const uint4*)(Bw + (size_t)br * DD + k0 + bf * 8);
        };

        float qacc[2][4][4];
        #pragma unroll
        for (int mi = 0; mi < 2; mi++)
            #pragma unroll
            for (int ni = 0; ni < 4; ni++)
                #pragma unroll
                for (int r = 0; r < 4; r++) qacc[mi][ni][r] = 0.f;

        loadQA(0);
        loadQB(0);

        #pragma unroll 1
        for (int s = 0; s < 16; s++) {
            uint32_t* Asb = (s & 1) ? As1 : As0;
            uint32_t* Bsb = (s & 1) ? Bs1 : Bs0;
            #pragma unroll
            for (int i = 0; i < 4; i++)
                *(uint2*)&Asb[(ar + i * 32) * 20 + af4 * 2] =
                    make_uint2(packh2(aR[i].x, aR[i].y), packh2(aR[i].z, aR[i].w));
            *(uint4*)&Bsb[br * 20 + bf * 4] = bR;
            __syncthreads();

            if (s < 15) { loadQA((s + 1) * 32); loadQB((s + 1) * 32); }

            #pragma unroll
            for (int ks = 0; ks < 2; ks++) {
                const int ko = ks * 8;
                uint32_t af[2][4];
                #pragma unroll
                for (int mi = 0; mi < 2; mi++) {
                    const int mb = wm * 32 + mi * 16;
                    af[mi][0] = Asb[(mb + g) * 20 + ko + t];
                    af[mi][1] = Asb[(mb + g + 8) * 20 + ko + t];
                    af[mi][2] = Asb[(mb + g) * 20 + ko + t + 4];
                    af[mi][3] = Asb[(mb + g + 8) * 20 + ko + t + 4];
                }
                #pragma unroll
                for (int ni = 0; ni < 4; ni++) {
                    const int nb = wn * 32 + ni * 8;
                    uint32_t bf2[2];
                    bf2[0] = Bsb[(nb + g) * 20 + ko + t];
                    bf2[1] = Bsb[(nb + g) * 20 + ko + t + 4];
                    mma_f16(qacc[0][ni], af[0], bf2);
                    mma_f16(qacc[1][ni], af[1], bf2);
                }
            }
        }

        // epilogue: qacc -> Qs (bank-conflict-free: 4g+t covers all banks)
        #pragma unroll
        for (int mi = 0; mi < 2; mi++) {
            const int rr = wm * 32 + mi * 16 + g;
            #pragma unroll
            for (int ni = 0; ni < 4; ni++) {
                const int cw = wn * 16 + ni * 4 + t;
                Qs[rr * 36 + cw] = packh2(qacc[mi][ni][0], qacc[mi][ni][1]);
                Qs[(rr + 8) * 36 + cw] = packh2(qacc[mi][ni][2], qacc[mi][ni][3]);
            }
        }
        __syncthreads();   // Qs visible; staging reads complete (KsB/VsB free)
    }

    // ---- main loop (round-11 proven) ----
    float oacc[8][4];
    #pragma unroll
    for (int ni = 0; ni < 8; ni++)
        #pragma unroll
        for (int r = 0; r < 4; r++) oacc[ni][r] = 0.f;
    float m0 = -CUDART_INF_F, m1 = -CUDART_INF_F, l0 = 0.f, l1 = 0.f;

    const int row0 = tile * 128 + w * 16 + g;
    const int lim0 = row0 >> 2;
    const int lim1 = (row0 + 8) >> 2;

    #pragma unroll 1
    for (int c = 0; c < nch; c++) {
        const int k0 = c * 64;
        uint32_t* Ks = KsB + (c & 1) * (64 * 36);
        uint32_t* Vs = VsB + (c & 1) * (32 * 68);

        #pragma unroll
        for (int i = 0; i < 2; i++)
            *(uint4*)&Ks[(kr8 + i * 32) * 36 + kc8 * 4] = kR[i];
        #pragma unroll
        for (int i = 0; i < 2; i++) {
            uint4 uu;
            uu.x = __byte_perm(vaR[i].x, vbR[i].x, 0x5410);
            uu.y = __byte_perm(vaR[i].x, vbR[i].x, 0x7632);
            uu.z = __byte_perm(vaR[i].y, vbR[i].y, 0x5410);
            uu.w = __byte_perm(vaR[i].y, vbR[i].y, 0x7632);
            *(uint4*)&Vs[(vjp + i * 16) * 68 + vd4 * 4] = uu;
        }
        __syncthreads();
        if (c + 1 < nch) loadKV(k0 + 64);

        float pf[8][4];
        #pragma unroll
        for (int ni = 0; ni < 8; ni++)
            #pragma unroll
            for (int r = 0; r < 4; r++) pf[ni][r] = 0.f;

        const int mb = w * 16;
        #pragma unroll
        for (int kt = 0; kt < 4; kt++) {
            const int ko = kt * 8;
            uint32_t af[4];
            af[0] = Qs[(mb + g) * 36 + ko + t];
            af[1] = Qs[(mb + g + 8) * 36 + ko + t];
            af[2] = Qs[(mb + g) * 36 + ko + t + 4];
            af[3] = Qs[(mb + g + 8) * 36 + ko + t + 4];
            #pragma unroll
            for (int ni = 0; ni < 8; ni++) {
                uint32_t bf2[2];
                bf2[0] = Ks[(ni * 8 + g) * 36 + ko + t];
                bf2[1] = Ks[(ni * 8 + g) * 36 + ko + t + 4];
                mma_f16(pf[ni], af, bf2);
            }
        }

        if (c == nch - 1) {
            #pragma unroll
            for (int ni = 0; ni < 8; ni++) {
                const int j = k0 + ni * 8 + 2 * t;
                if (j > lim0)     pf[ni][0] = -CUDART_INF_F;
                if (j + 1 > lim0) pf[ni][1] = -CUDART_INF_F;
                if (j > lim1)     pf[ni][2] = -CUDART_INF_F;
                if (j + 1 > lim1) pf[ni][3] = -CUDART_INF_F;
            }
        }

        float mx0 = -CUDART_INF_F, mx1 = -CUDART_INF_F;
        #pragma unroll
        for (int ni = 0; ni < 8; ni++) {
            mx0 = fmaxf(mx0, fmaxf(pf[ni][0], pf[ni][1]));
            mx1 = fmaxf(mx1, fmaxf(pf[ni][2], pf[ni][3]));
        }
        mx0 = fmaxf(mx0, __shfl_xor_sync(0xffffffffu, mx0, 1));
        mx0 = fmaxf(mx0, __shfl_xor_sync(0xffffffffu, mx0, 2));
        mx1 = fmaxf(mx1, __shfl_xor_sync(0xffffffffu, mx1, 1));
        mx1 = fmaxf(mx1, __shfl_xor_sync(0xffffffffu, mx1, 2));

        const float mn0 = fmaxf(m0, mx0), mn1 = fmaxf(m1, mx1);
        const float al0 = __expf(m0 - mn0), al1 = __expf(m1 - mn1);
        m0 = mn0; m1 = mn1;

        float rs0 = 0.f, rs1 = 0.f;
        #pragma unroll
        for (int ni = 0; ni < 8; ni++) {
            pf[ni][0] = __expf(pf[ni][0] - mn0);
            pf[ni][1] = __expf(pf[ni][1] - mn0);
            pf[ni][2] = __expf(pf[ni][2] - mn1);
            pf[ni][3] = __expf(pf[ni][3] - mn1);
            rs0 += pf[ni][0] + pf[ni][1];
            rs1 += pf[ni][2] + pf[ni][3];
        }
        rs0 += __shfl_xor_sync(0xffffffffu, rs0, 1);
        rs0 += __shfl_xor_sync(0xffffffffu, rs0, 2);
        rs1 += __shfl_xor_sync(0xffffffffu, rs1, 1);
        rs1 += __shfl_xor_sync(0xffffffffu, rs1, 2);
        l0 = l0 * al0 + rs0;
        l1 = l1 * al1 + rs1;

        #pragma unroll
        for (int ni = 0; ni < 8; ni++) {
            oacc[ni][0] *= al0; oacc[ni][1] *= al0;
            oacc[ni][2] *= al1; oacc[ni][3] *= al1;
        }

        #pragma unroll
        for (int kt = 0; kt < 4; kt++) {
            uint32_t a[4];
            a[0] = packh2(pf[2 * kt][0],     pf[2 * kt][1]);
            a[1] = packh2(pf[2 * kt][2],     pf[2 * kt][3]);
            a[2] = packh2(pf[2 * kt + 1][0], pf[2 * kt + 1][1]);
            a[3] = packh2(pf[2 * kt + 1][2], pf[2 * kt + 1][3]);
            const int jp0 = 8 * kt + t;
            #pragma unroll
            for (int ni = 0; ni < 8; ni++) {
                uint32_t bf2[2];
                bf2[0] = Vs[jp0 * 68 + ni * 8 + g];
                bf2[1] = Vs[(jp0 + 4) * 68 + ni * 8 + g];
                mma_f16(oacc[ni], a, bf2);
            }
        }
    }

    const float inv0 = 1.f / l0, inv1 = 1.f / l1;
    const int lr0 = w * 16 + g;
    float s0 = 0.f, q0 = 0.f, s1 = 0.f, q1 = 0.f;
    #pragma unroll
    for (int ni = 0; ni < 8; ni++) {
        const int cc = ni * 8 + 2 * t;
        const float f00 = oacc[ni][0] * inv0, f01 = oacc[ni][1] * inv0;
        const float f10 = oacc[ni][2] * inv1, f11 = oacc[ni][3] * inv1;
        s0 += f00 + f01; q0 += f00 * f00 + f01 * f01;
        s1 += f10 + f11; q1 += f10 * f10 + f11 * f11;
        *(uint32_t*)(O + qbase + (size_t)lr0 * DD + cc) = packh2(f00, f01);
        *(uint32_t*)(O + qbase + (size_t)(lr0 + 8) * DD + cc) = packh2(f10, f11);
    }
    s0 += __shfl_xor_sync(0xffffffffu, s0, 1);
    s0 += __shfl_xor_sync(0xffffffffu, s0, 2);
    q0 += __shfl_xor_sync(0xffffffffu, q0, 1);
    q0 += __shfl_xor_sync(0xffffffffu, q0, 2);
    s1 += __shfl_xor_sync(0xffffffffu, s1, 1);
    s1 += __shfl_xor_sync(0xffffffffu, s1, 2);
    q1 += __shfl_xor_sync(0xffffffffu, q1, 1);
    q1 += __shfl_xor_sync(0xffffffffu, q1, 2);
    if (t == 0) {
        const int gr0 = b * NQ + tile * 128 + lr0;
        psum[gr0 * HH + h] = make_float2(s0, q0);
        psum[(gr0 + 8) * HH + h] = make_float2(s1, q1);
    }
}

// ---------------------------------------------------------------------------
// Launch
// ---------------------------------------------------------------------------
extern "C" void kernel_launch(void* const* d_in, const int* in_sizes, int n_in,
                              void* d_out, int out_size)
{
    (void)in_sizes; (void)n_in; (void)out_size;

    const float* q     = (const float*)d_in[0];
    const float* kv    = (const float*)d_in[1];
    const float* Wq    = (const float*)d_in[2];
    const float* Wk    = (const float*)d_in[3];
    const float* Wv    = (const float*)d_in[4];
    const float* Wo    = (const float*)d_in[5];
    const float* bo    = (const float*)d_in[6];
    const float* gamma = (const float*)d_in[7];
    const float* beta  = (const float*)d_in[8];
    float* out = (float*)d_out;

    __half *kh, *vh, *attn, *wt;
    float2 *psum, *uvp;
    float *du, *dvb;
    cudaGetSymbolAddress((void**)&kh,   g_kh);
    cudaGetSymbolAddress((void**)&vh,   g_vh);
    cudaGetSymbolAddress((void**)&attn, g_attn);
    cudaGetSymbolAddress((void**)&psum, g_psum);
    cudaGetSymbolAddress((void**)&wt,   g_wt);
    cudaGetSymbolAddress((void**)&uvp,  g_uvpart);
    cudaGetSymbolAddress((void**)&du,   g_u);
    cudaGetSymbolAddress((void**)&dvb,  g_vb);

    cudaFuncSetAttribute(attn_f16,
                         cudaFuncAttributeMaxDynamicSharedMemorySize,
                         ATTN_SMEM_BYTES);

    const __half* wtq = wt;
    const __half* wtk = wt + 1 * DD * DD;
    const __half* wtv = wt + 2 * DD * DD;
    const __half* wto = wt + 3 * DD * DD;

    // Weight prep
    {
        dim3 grid(DD / 32, DD / 32, 4);
        transpose_w<<<grid, dim3(32, 8)>>>(Wq, Wk, Wv, Wo, gamma, wt);
    }
    {
        dim3 grid(DD / 256, 8);
        uv_part<<<grid, 256>>>(Wo, gamma, beta, uvp);
    }
    uv_reduce<<<DD / 256, 256>>>(uvp, bo, du, dvb);

    // K/V projections (128 CTAs, single wave)
    {
        dim3 grid(DD / 128, 32, 1);
        proj_gemm<<<grid, 256>>>(kv, wtk, wtv, kh, vh);
    }
    // Attention with fused Q-projection
    {
        dim3 grid(NQ / 128, HH, BB);
        attn_f16<<<grid, 256, ATTN_SMEM_BYTES>>>(q, wtq, kh, vh, attn, psum);
    }
    // Output projection (LN factored into epilogue)
    {
        dim3 grid(DD / 128, (BB * NQ) / 128, 1);
        out_gemm<<<grid, 256>>>(attn, wto, du, dvb, psum, out);
    }
}

// round 15
// speedup vs baseline: 1.0999x; 1.0999x over previous
#include <cuda_runtime.h>
#include <cuda_fp16.h>
#include <math_constants.h>
#include <cstdint>
#include <cstddef>

#define BB 2
#define NQ 4096
#define NKV 1024
#define DD 512
#define HH 8
#define DH 64
#define LN_EPS 1e-5f

// ---------------------------------------------------------------------------
// Scratch
// ---------------------------------------------------------------------------
__device__ __half g_qh[BB * NQ * DD];
__device__ __half g_kh[BB * NKV * DD];
__device__ __half g_vh[BB * NKV * DD];
__device__ __half g_attn[BB * NQ * DD];
__device__ float2 g_psum[BB * NQ * HH];
__device__ __half g_wt[4 * DD * DD];     // W^T fp16 (Wq/8, Wo*gamma folded)
__device__ float2 g_uvpart[8 * DD];
__device__ float  g_u[DD];
__device__ float  g_vb[DD];

// ---------------------------------------------------------------------------
// helpers
// ---------------------------------------------------------------------------
__device__ __forceinline__ uint32_t packh2(float lo, float hi) {
    uint32_t r;
    asm("cvt.rn.f16x2.f32 %0, %1, %2;" : "=r"(r) : "f"(hi), "f"(lo));
    return r;
}

__device__ __forceinline__ void mma_f16(float d[4], const uint32_t a[4],
                                        const uint32_t b[2]) {
    asm("mma.sync.aligned.m16n8k16.row.col.f32.f16.f16.f32 "
        "{%0,%1,%2,%3},{%4,%5,%6,%7},{%8,%9},{%0,%1,%2,%3};"
        : "+f"(d[0]), "+f"(d[1]), "+f"(d[2]), "+f"(d[3])
        : "r"(a[0]), "r"(a[1]), "r"(a[2]), "r"(a[3]), "r"(b[0]), "r"(b[1]));
}

// ---------------------------------------------------------------------------
// Weight transpose + fp16 convert: Wt[z][n][k] = fp16(W_z[k][n] * scale_z(k))
// ---------------------------------------------------------------------------
__global__ void __launch_bounds__(256) transpose_w(
    const float* __restrict__ Wq, const float* __restrict__ Wk,
    const float* __restrict__ Wv, const float* __restrict__ Wo,
    const float* __restrict__ gamma, __half* __restrict__ Wt)
{
    __shared__ float t[32][33];
    const int z = blockIdx.z;
    const float* W = (z == 0) ? Wq : (z == 1) ? Wk : (z == 2) ? Wv : Wo;
    __half* T = Wt + (size_t)z * DD * DD;
    const int tx = threadIdx.x, ty = threadIdx.y;
    const int kb = blockIdx.x * 32, nb = blockIdx.y * 32;
    #pragma unroll
    for (int j = 0; j < 4; j++) {
        const int k = kb + ty + j * 8;
        float sc = 1.0f;
        if (z == 0) sc = 0.125f;
        else if (z == 3) sc = gamma[k];
        t[ty + j * 8][tx] = W[(size_t)k * DD + nb + tx] * sc;
    }
    __syncthreads();
    #pragma unroll
    for (int j = 0; j < 4; j++)
        T[(size_t)(nb + ty + j * 8) * DD + kb + tx] =
            __float2half_rn(t[tx][ty + j * 8]);
}

// ---------------------------------------------------------------------------
// Split-K u/v partials + reduce
// ---------------------------------------------------------------------------
__global__ void __launch_bounds__(256) uv_part(
    const float* __restrict__ Wo, const float* __restrict__ gamma,
    const float* __restrict__ beta, float2* __restrict__ part)
{
    const int n = blockIdx.x * 256 + threadIdx.x;
    const int ks = blockIdx.y * 64;
    float su = 0.f, sv = 0.f;
    #pragma unroll 4
    for (int k = ks; k < ks + 64; k++) {
        const float w = Wo[(size_t)k * DD + n];
        su = fmaf(gamma[k], w, su);
        sv = fmaf(beta[k], w, sv);
    }
    part[blockIdx.y * DD + n] = make_float2(su, sv);
}

__global__ void __launch_bounds__(256) uv_reduce(
    const float2* __restrict__ part, const float* __restrict__ bo,
    float* __restrict__ u, float* __restrict__ vb)
{
    const int n = blockIdx.x * 256 + threadIdx.x;
    float su = 0.f, sv = 0.f;
    #pragma unroll
    for (int s = 0; s < 8; s++) {
        const float2 p = part[s * DD + n];
        su += p.x; sv += p.y;
    }
    u[n] = su;
    vb[n] = sv + bo[n];
}

// ---------------------------------------------------------------------------
// Merged projection GEMM (fp16 out), double-buffered smem.
// __launch_bounds__(256, 2) caps regs at 124 -> 2 CTAs/SM (was 126 -> 1).
// blockIdx.y: [0,64) Q, [64,80) K, [80,96) V.
// ---------------------------------------------------------------------------
__global__ void __launch_bounds__(256, 2) proj_gemm(
    const float* __restrict__ Aq, const float* __restrict__ Akv,
    const __half* __restrict__ WtQ, const __half* __restrict__ WtK,
    const __half* __restrict__ WtV,
    __half* __restrict__ Cq, __half* __restrict__ Ck, __half* __restrict__ Cv)
{
    __shared__ uint32_t As[2][128 * 20];
    __shared__ uint32_t Bs[2][128 * 20];

    const int ty = blockIdx.y;
    const float* __restrict__ A;
    const __half* __restrict__ Wt;
    __half* __restrict__ C;
    int row0;
    if (ty < 64)      { A = Aq;  Wt = WtQ; C = Cq; row0 = ty * 128; }
    else if (ty < 80) { A = Akv; Wt = WtK; C = Ck; row0 = (ty - 64) * 128; }
    else              { A = Akv; Wt = WtV; C = Cv; row0 = (ty - 80) * 128; }

    const int tid = threadIdx.x;
    const int lane = tid & 31;
    const int g = lane >> 2, t = lane & 3;
    const int w = tid >> 5;
    const int wm = w >> 1, wn = w & 1;
    const int col0 = blockIdx.x * 128;

    const int ar = tid >> 3;
    const int af4 = tid & 7;
    const int br = tid >> 2;
    const int bf = tid & 3;

    float4 aR[4];
    uint4 bR[2];

    auto loadA = [&](int k0) {
        #pragma unroll
        for (int i = 0; i < 4; i++)
            aR[i] = *(const float4*)(A + (size_t)(row0 + ar + i * 32) * DD + k0 + af4 * 4);
    };
    auto loadB = [&](int k0) {
        #pragma unroll
        for (int i = 0; i < 2; i++)
            bR[i] = *(const uint4*)(Wt + (size_t)(col0 + br + i * 64) * DD + k0 + bf * 8);
    };

    float acc[2][8][4];
    #pragma unroll
    for (int mi = 0; mi < 2; mi++)
        #pragma unroll
        for (int ni = 0; ni < 8; ni++)
            #pragma unroll
            for (int r = 0; r < 4; r++) acc[mi][ni][r] = 0.f;

    loadA(0);
    loadB(0);

    #pragma unroll 1
    for (int s = 0; s < 16; s++) {
        const int buf = s & 1;
        #pragma unroll
        for (int i = 0; i < 4; i++)
            *(uint2*)&As[buf][(ar + i * 32) * 20 + af4 * 2] =
                make_uint2(packh2(aR[i].x, aR[i].y), packh2(aR[i].z, aR[i].w));
        #pragma unroll
        for (int i = 0; i < 2; i++)
            *(uint4*)&Bs[buf][(br + i * 64) * 20 + bf * 4] = bR[i];
        __syncthreads();

        if (s < 15) { loadA((s + 1) * 32); loadB((s + 1) * 32); }

        #pragma unroll
        for (int ks = 0; ks < 2; ks++) {
            const int ko = ks * 8;
            uint32_t af[2][4];
            #pragma unroll
            for (int mi = 0; mi < 2; mi++) {
                const int mb = wm * 32 + mi * 16;
                af[mi][0] = As[buf][(mb + g) * 20 + ko + t];
                af[mi][1] = As[buf][(mb + g + 8) * 20 + ko + t];
                af[mi][2] = As[buf][(mb + g) * 20 + ko + t + 4];
                af[mi][3] = As[buf][(mb + g + 8) * 20 + ko + t + 4];
            }
            #pragma unroll
            for (int ni = 0; ni < 8; ni++) {
                const int nb = wn * 64 + ni * 8;
                uint32_t bf2[2];
                bf2[0] = Bs[buf][(nb + g) * 20 + ko + t];
                bf2[1] = Bs[buf][(nb + g) * 20 + ko + t + 4];
                mma_f16(acc[0][ni], af[0], bf2);
                mma_f16(acc[1][ni], af[1], bf2);
            }
        }
    }

    #pragma unroll
    for (int mi = 0; mi < 2; mi++) {
        const int rr0 = row0 + wm * 32 + mi * 16 + g;
        #pragma unroll
        for (int ni = 0; ni < 8; ni++) {
            const int cc = col0 + wn * 64 + ni * 8 + 2 * t;
            *(uint32_t*)(C + (size_t)rr0 * DD + cc) =
                packh2(acc[mi][ni][0], acc[mi][ni][1]);
            *(uint32_t*)(C + (size_t)(rr0 + 8) * DD + cc) =
                packh2(acc[mi][ni][2], acc[mi][ni][3]);
        }
    }
}

// ---------------------------------------------------------------------------
// Output GEMM, LN factored: C = rs*(A@W') + sh*u + vb.
// __launch_bounds__(256, 2) -> 2 CTAs/SM.
// ---------------------------------------------------------------------------
__global__ void __launch_bounds__(256, 2) out_gemm(
    const __half* __restrict__ A, const __half* __restrict__ Wt,
    const float* __restrict__ u, const float* __restrict__ vb,
    const float2* __restrict__ psum, float* __restrict__ C)
{
    __shared__ uint32_t As[2][128 * 20];
    __shared__ uint32_t Bs[2][128 * 20];

    const int tid = threadIdx.x;
    const int lane = tid & 31;
    const int g = lane >> 2, t = lane & 3;
    const int w = tid >> 5;
    const int wm = w >> 1, wn = w & 1;
    const int row0 = blockIdx.y * 128, col0 = blockIdx.x * 128;

    const int cr = tid >> 2;
    const int co = tid & 3;

    float rs_[2][2], sh_[2][2];
    #pragma unroll
    for (int mi = 0; mi < 2; mi++)
        #pragma unroll
        for (int hh = 0; hh < 2; hh++) {
            const int gr = row0 + wm * 32 + mi * 16 + hh * 8 + g;
            float S = 0.f, Q = 0.f;
            #pragma unroll
            for (int hd = 0; hd < HH; hd++) {
                const float2 ps = psum[gr * HH + hd];
                S += ps.x; Q += ps.y;
            }
            const float mean = S * (1.f / DD);
            const float var = Q * (1.f / DD) - mean * mean;
            const float rs = rsqrtf(var + LN_EPS);
            rs_[mi][hh] = rs;
            sh_[mi][hh] = -mean * rs;
        }

    uint4 aR[2], bR[2];

    auto loadAB = [&](int k0) {
        #pragma unroll
        for (int i = 0; i < 2; i++) {
            aR[i] = *(const uint4*)(A + (size_t)(row0 + cr + i * 64) * DD + k0 + co * 8);
            bR[i] = *(const uint4*)(Wt + (size_t)(col0 + cr + i * 64) * DD + k0 + co * 8);
        }
    };

    float acc[2][8][4];
    #pragma unroll
    for (int mi = 0; mi < 2; mi++)
        #pragma unroll
        for (int ni = 0; ni < 8; ni++)
            #pragma unroll
            for (int r = 0; r < 4; r++) acc[mi][ni][r] = 0.f;

    loadAB(0);

    #pragma unroll 1
    for (int s = 0; s < 16; s++) {
        const int buf = s & 1;
        #pragma unroll
        for (int i = 0; i < 2; i++) {
            *(uint4*)&As[buf][(cr + i * 64) * 20 + co * 4] = aR[i];
            *(uint4*)&Bs[buf][(cr + i * 64) * 20 + co * 4] = bR[i];
        }
        __syncthreads();

        if (s < 15) loadAB((s + 1) * 32);

        #pragma unroll
        for (int ks = 0; ks < 2; ks++) {
            const int ko = ks * 8;
            uint32_t af[2][4];
            #pragma unroll
            for (int mi = 0; mi < 2; mi++) {
                const int mb = wm * 32 + mi * 16;
                af[mi][0] = As[buf][(mb + g) * 20 + ko + t];
                af[mi][1] = As[buf][(mb + g + 8) * 20 + ko + t];
                af[mi][2] = As[buf][(mb + g) * 20 + ko + t + 4];
                af[mi][3] = As[buf][(mb + g + 8) * 20 + ko + t + 4];
            }
            #pragma unroll
            for (int ni = 0; ni < 8; ni++) {
                const int nb = wn * 64 + ni * 8;
                uint32_t bf2[2];
                bf2[0] = Bs[buf][(nb + g) * 20 + ko + t];
                bf2[1] = Bs[buf][(nb + g) * 20 + ko + t + 4];
                mma_f16(acc[0][ni], af[0], bf2);
                mma_f16(acc[1][ni], af[1], bf2);
            }
        }
    }

    #pragma unroll
    for (int mi = 0; mi < 2; mi++) {
        const int rr0 = row0 + wm * 32 + mi * 16 + g;
        #pragma unroll
        for (int ni = 0; ni < 8; ni++) {
            const int cc = col0 + wn * 64 + ni * 8 + 2 * t;
            const float2 u2 = *(const float2*)(u + cc);
            const float2 vb2 = *(const float2*)(vb + cc);
            float2 v0, v1;
            v0.x = fmaf(acc[mi][ni][0], rs_[mi][0], fmaf(sh_[mi][0], u2.x, vb2.x));
            v0.y = fmaf(acc[mi][ni][1], rs_[mi][0], fmaf(sh_[mi][0], u2.y, vb2.y));
            v1.x = fmaf(acc[mi][ni][2], rs_[mi][1], fmaf(sh_[mi][1], u2.x, vb2.x));
            v1.y = fmaf(acc[mi][ni][3], rs_[mi][1], fmaf(sh_[mi][1], u2.y, vb2.y));
            *(float2*)(C + (size_t)rr0 * DD + cc) = v0;
            *(float2*)(C + (size_t)(rr0 + 8) * DD + cc) = v1;
        }
    }
}

// ---------------------------------------------------------------------------
// Flash attention (round-11 proven): reg prefetch + double-buffered K/V,
// fp16 output + per-(row, head) LN partial sums.
// ---------------------------------------------------------------------------
#define ATTN_SMEM_BYTES ((128 * 36 + 2 * 64 * 36 + 2 * 32 * 68) * 4)

__global__ void __launch_bounds__(256) attn_f16(
    const __half* __restrict__ Qh, const __half* __restrict__ Kh,
    const __half* __restrict__ Vh, __half* __restrict__ O,
    float2* __restrict__ psum)
{
    extern __shared__ uint32_t smd[];
    uint32_t* Qs  = smd;
    uint32_t* KsB = Qs + 128 * 36;
    uint32_t* VsB = KsB + 2 * 64 * 36;

    const int tile = (NQ / 128 - 1) - blockIdx.x;
    const int h = blockIdx.y, b = blockIdx.z;
    const int tid = threadIdx.x;
    const int lane = tid & 31;
    const int g = lane >> 2, t = lane & 3;
    const int w = tid >> 5;

    const size_t qbase = ((size_t)b * NQ + (size_t)tile * 128) * DD + (size_t)h * DH;
    const size_t kvbase = (size_t)b * NKV * DD + (size_t)h * DH;

    #pragma unroll
    for (int i = 0; i < 4; i++) {
        const int idx = tid + i * 256;
        const int r = idx >> 3, c = idx & 7;
        const uint4 uu = *(const uint4*)(Qh + qbase + (size_t)r * DD + c * 8);
        *(uint4*)&Qs[r * 36 + c * 4] = uu;
    }

    float oacc[8][4];
    #pragma unroll
    for (int ni = 0; ni < 8; ni++)
        #pragma unroll
        for (int r = 0; r < 4; r++) oacc[ni][r] = 0.f;
    float m0 = -CUDART_INF_F, m1 = -CUDART_INF_F, l0 = 0.f, l1 = 0.f;

    const int row0 = tile * 128 + w * 16 + g;
    const int lim0 = row0 >> 2;
    const int lim1 = (row0 + 8) >> 2;
    const int nch = (32 * tile + 95) >> 6;

    const int kr8 = tid >> 3, kc8 = tid & 7;
    const int vjp = tid >> 4, vd4 = tid & 15;
    uint4 kR[2];
    uint2 vaR[2], vbR[2];

    auto loadKV = [&](int k0) {
        #pragma unroll
        for (int i = 0; i < 2; i++)
            kR[i] = *(const uint4*)(Kh + kvbase + (size_t)(k0 + kr8 + i * 32) * DD + kc8 * 8);
        #pragma unroll
        for (int i = 0; i < 2; i++) {
            const int jp = vjp + i * 16;
            vaR[i] = *(const uint2*)(Vh + kvbase + (size_t)(k0 + 2 * jp) * DD + vd4 * 4);
            vbR[i] = *(const uint2*)(Vh + kvbase + (size_t)(k0 + 2 * jp + 1) * DD + vd4 * 4);
        }
    };

    loadKV(0);

    #pragma unroll 1
    for (int c = 0; c < nch; c++) {
        const int k0 = c * 64;
        uint32_t* Ks = KsB + (c & 1) * (64 * 36);
        uint32_t* Vs = VsB + (c & 1) * (32 * 68);

        #pragma unroll
        for (int i = 0; i < 2; i++)
            *(uint4*)&Ks[(kr8 + i * 32) * 36 + kc8 * 4] = kR[i];
        #pragma unroll
        for (int i = 0; i < 2; i++) {
            uint4 uu;
            uu.x = __byte_perm(vaR[i].x, vbR[i].x, 0x5410);
            uu.y = __byte_perm(vaR[i].x, vbR[i].x, 0x7632);
            uu.z = __byte_perm(vaR[i].y, vbR[i].y, 0x5410);
            uu.w = __byte_perm(vaR[i].y, vbR[i].y, 0x7632);
            *(uint4*)&Vs[(vjp + i * 16) * 68 + vd4 * 4] = uu;
        }
        __syncthreads();
        if (c + 1 < nch) loadKV(k0 + 64);

        float pf[8][4];
        #pragma unroll
        for (int ni = 0; ni < 8; ni++)
            #pragma unroll
            for (int r = 0; r < 4; r++) pf[ni][r] = 0.f;

        const int mb = w * 16;
        #pragma unroll
        for (int kt = 0; kt < 4; kt++) {
            const int ko = kt * 8;
            uint32_t af[4];
            af[0] = Qs[(mb + g) * 36 + ko + t];
            af[1] = Qs[(mb + g + 8) * 36 + ko + t];
            af[2] = Qs[(mb + g) * 36 + ko + t + 4];
            af[3] = Qs[(mb + g + 8) * 36 + ko + t + 4];
            #pragma unroll
            for (int ni = 0; ni < 8; ni++) {
                uint32_t bf2[2];
                bf2[0] = Ks[(ni * 8 + g) * 36 + ko + t];
                bf2[1] = Ks[(ni * 8 + g) * 36 + ko + t + 4];
                mma_f16(pf[ni], af, bf2);
            }
        }

        if (c == nch - 1) {
            #pragma unroll
            for (int ni = 0; ni < 8; ni++) {
                const int j = k0 + ni * 8 + 2 * t;
                if (j > lim0)     pf[ni][0] = -CUDART_INF_F;
                if (j + 1 > lim0) pf[ni][1] = -CUDART_INF_F;
                if (j > lim1)     pf[ni][2] = -CUDART_INF_F;
                if (j + 1 > lim1) pf[ni][3] = -CUDART_INF_F;
            }
        }

        float mx0 = -CUDART_INF_F, mx1 = -CUDART_INF_F;
        #pragma unroll
        for (int ni = 0; ni < 8; ni++) {
            mx0 = fmaxf(mx0, fmaxf(pf[ni][0], pf[ni][1]));
            mx1 = fmaxf(mx1, fmaxf(pf[ni][2], pf[ni][3]));
        }
        mx0 = fmaxf(mx0, __shfl_xor_sync(0xffffffffu, mx0, 1));
        mx0 = fmaxf(mx0, __shfl_xor_sync(0xffffffffu, mx0, 2));
        mx1 = fmaxf(mx1, __shfl_xor_sync(0xffffffffu, mx1, 1));
        mx1 = fmaxf(mx1, __shfl_xor_sync(0xffffffffu, mx1, 2));

        const float mn0 = fmaxf(m0, mx0), mn1 = fmaxf(m1, mx1);
        const float al0 = __expf(m0 - mn0), al1 = __expf(m1 - mn1);
        m0 = mn0; m1 = mn1;

        float rs0 = 0.f, rs1 = 0.f;
        #pragma unroll
        for (int ni = 0; ni < 8; ni++) {
            pf[ni][0] = __expf(pf[ni][0] - mn0);
            pf[ni][1] = __expf(pf[ni][1] - mn0);
            pf[ni][2] = __expf(pf[ni][2] - mn1);
            pf[ni][3] = __expf(pf[ni][3] - mn1);
            rs0 += pf[ni][0] + pf[ni][1];
            rs1 += pf[ni][2] + pf[ni][3];
        }
        rs0 += __shfl_xor_sync(0xffffffffu, rs0, 1);
        rs0 += __shfl_xor_sync(0xffffffffu, rs0, 2);
        rs1 += __shfl_xor_sync(0xffffffffu, rs1, 1);
        rs1 += __shfl_xor_sync(0xffffffffu, rs1, 2);
        l0 = l0 * al0 + rs0;
        l1 = l1 * al1 + rs1;

        #pragma unroll
        for (int ni = 0; ni < 8; ni++) {
            oacc[ni][0] *= al0; oacc[ni][1] *= al0;
            oacc[ni][2] *= al1; oacc[ni][3] *= al1;
        }

        #pragma unroll
        for (int kt = 0; kt < 4; kt++) {
            uint32_t a[4];
            a[0] = packh2(pf[2 * kt][0],     pf[2 * kt][1]);
            a[1] = packh2(pf[2 * kt][2],     pf[2 * kt][3]);
            a[2] = packh2(pf[2 * kt + 1][0], pf[2 * kt + 1][1]);
            a[3] = packh2(pf[2 * kt + 1][2], pf[2 * kt + 1][3]);
            const int jp0 = 8 * kt + t;
            #pragma unroll
            for (int ni = 0; ni < 8; ni++) {
                uint32_t bf2[2];
                bf2[0] = Vs[jp0 * 68 + ni * 8 + g];
                bf2[1] = Vs[(jp0 + 4) * 68 + ni * 8 + g];
                mma_f16(oacc[ni], a, bf2);
            }
        }
    }

    const float inv0 = 1.f / l0, inv1 = 1.f / l1;
    const int lr0 = w * 16 + g;
    float s0 = 0.f, q0 = 0.f, s1 = 0.f, q1 = 0.f;
    #pragma unroll
    for (int ni = 0; ni < 8; ni++) {
        const int cc = ni * 8 + 2 * t;
        const float f00 = oacc[ni][0] * inv0, f01 = oacc[ni][1] * inv0;
        const float f10 = oacc[ni][2] * inv1, f11 = oacc[ni][3] * inv1;
        s0 += f00 + f01; q0 += f00 * f00 + f01 * f01;
        s1 += f10 + f11; q1 += f10 * f10 + f11 * f11;
        *(uint32_t*)(O + qbase + (size_t)lr0 * DD + cc) = packh2(f00, f01);
        *(uint32_t*)(O + qbase + (size_t)(lr0 + 8) * DD + cc) = packh2(f10, f11);
    }
    s0 += __shfl_xor_sync(0xffffffffu, s0, 1);
    s0 += __shfl_xor_sync(0xffffffffu, s0, 2);
    q0 += __shfl_xor_sync(0xffffffffu, q0, 1);
    q0 += __shfl_xor_sync(0xffffffffu, q0, 2);
    s1 += __shfl_xor_sync(0xffffffffu, s1, 1);
    s1 += __shfl_xor_sync(0xffffffffu, s1, 2);
    q1 += __shfl_xor_sync(0xffffffffu, q1, 1);
    q1 += __shfl_xor_sync(0xffffffffu, q1, 2);
    if (t == 0) {
        const int gr0 = b * NQ + tile * 128 + lr0;
        psum[gr0 * HH + h] = make_float2(s0, q0);
        psum[(gr0 + 8) * HH + h] = make_float2(s1, q1);
    }
}

// ---------------------------------------------------------------------------
// Launch
// ---------------------------------------------------------------------------
extern "C" void kernel_launch(void* const* d_in, const int* in_sizes, int n_in,
                              void* d_out, int out_size)
{
    (void)in_sizes; (void)n_in; (void)out_size;

    const float* q     = (const float*)d_in[0];
    const float* kv    = (const float*)d_in[1];
    const float* Wq    = (const float*)d_in[2];
    const float* Wk    = (const float*)d_in[3];
    const float* Wv    = (const float*)d_in[4];
    const float* Wo    = (const float*)d_in[5];
    const float* bo    = (const float*)d_in[6];
    const float* gamma = (const float*)d_in[7];
    const float* beta  = (const float*)d_in[8];
    float* out = (float*)d_out;

    __half *qh, *kh, *vh, *attn, *wt;
    float2 *psum, *uvp;
    float *du, *dvb;
    cudaGetSymbolAddress((void**)&qh,   g_qh);
    cudaGetSymbolAddress((void**)&kh,   g_kh);
    cudaGetSymbolAddress((void**)&vh,   g_vh);
    cudaGetSymbolAddress((void**)&attn, g_attn);
    cudaGetSymbolAddress((void**)&psum, g_psum);
    cudaGetSymbolAddress((void**)&wt,   g_wt);
    cudaGetSymbolAddress((void**)&uvp,  g_uvpart);
    cudaGetSymbolAddress((void**)&du,   g_u);
    cudaGetSymbolAddress((void**)&dvb,  g_vb);

    cudaFuncSetAttribute(attn_f16,
                         cudaFuncAttributeMaxDynamicSharedMemorySize,
                         ATTN_SMEM_BYTES);

    const __half* wtq = wt;
    const __half* wtk = wt + 1 * DD * DD;
    const __half* wtv = wt + 2 * DD * DD;
    const __half* wto = wt + 3 * DD * DD;

    // Weight prep
    {
        dim3 grid(DD / 32, DD / 32, 4);
        transpose_w<<<grid, dim3(32, 8)>>>(Wq, Wk, Wv, Wo, gamma, wt);
    }
    {
        dim3 grid(DD / 256, 8);
        uv_part<<<grid, 256>>>(Wo, gamma, beta, uvp);
    }
    uv_reduce<<<DD / 256, 256>>>(uvp, bo, du, dvb);

    // Projections (Q + K + V merged, 384 CTAs @ 2 CTAs/SM)
    {
        dim3 grid(DD / 128, 96, 1);
        proj_gemm<<<grid, 256>>>(q, kv, wtq, wtk, wtv, qh, kh, vh);
    }
    // Attention
    {
        dim3 grid(NQ / 128, HH, BB);
        attn_f16<<<grid, 256, ATTN_SMEM_BYTES>>>(qh, kh, vh, attn, psum);
    }
    // Output projection (LN factored into epilogue)
    {
        dim3 grid(DD / 128, (BB * NQ) / 128, 1);
        out_gemm<<<grid, 256>>>(attn, wto, du, dvb, psum, out);
    }
}